// round 2
// baseline (speedup 1.0000x reference)
#include <cuda_runtime.h>
#include <math.h>

// Problem constants
static constexpr int NN   = 100000;   // nodes
static constexpr int NE   = 1600000;  // edges
static constexpr int FIN  = 500;
static constexpr int HID  = 64;
static constexpr int NCLS = 40;

// ---------------- scratch (device globals; no cudaMalloc allowed) ----------
__device__ float g_dinv[NN];              // deg -> dinv (in place)
__device__ float g_h1s [NN * HID];        // h1 * dinv[row]; later relu(h)
__device__ float g_t1  [NN * HID];        // layer-1 aggregation accumulator
__device__ float g_gs  [NN * NCLS];       // g2 * dinv[row]
__device__ int   g_src [NE];
__device__ int   g_dst [NE];
__device__ int   g_is64;

// ---------------- edge-index dtype detection + conversion ------------------
// If the buffer holds int64 node ids (< 2^31, nonnegative), every odd int32
// word (the high half, little-endian) is zero. For int32 ids in [0,100000),
// 64 consecutive zeros is (1e-5)^64 — impossible.
__global__ void k_detect(const int* __restrict__ e) {
    if (threadIdx.x == 0 && blockIdx.x == 0) {
        int all0 = 1;
        #pragma unroll 1
        for (int i = 0; i < 64; i++) all0 &= (e[2 * i + 1] == 0);
        g_is64 = all0;
    }
}

__global__ void k_convert(const int* __restrict__ e) {
    int i = blockIdx.x * blockDim.x + threadIdx.x;
    if (i >= 2 * NE) return;
    int v = g_is64 ? e[2 * i] : e[i];   // low word of int64, or int32 directly
    if (i < NE) g_src[i] = v;
    else        g_dst[i - NE] = v;
}

// ---------------- degree / dinv --------------------------------------------
__global__ void k_deg_init() {
    int i = blockIdx.x * blockDim.x + threadIdx.x;
    if (i < NN) g_dinv[i] = 1.0f;   // self-loop contributes 1
}

__global__ void k_deg_count() {
    int e = blockIdx.x * blockDim.x + threadIdx.x;
    if (e < NE) atomicAdd(&g_dinv[g_dst[e]], 1.0f);
}

__global__ void k_make_dinv() {
    int i = blockIdx.x * blockDim.x + threadIdx.x;
    if (i < NN) g_dinv[i] = rsqrtf(g_dinv[i]);
}

// ---------------- GEMM1: h1s = (x @ W1) * dinv[row] ------------------------
// BM=64, BN=64(=HID), BK=32, 256 threads, 4x4 micro-tile per thread.
__global__ __launch_bounds__(256) void k_gemm1(const float* __restrict__ x,
                                               const float* __restrict__ W1) {
    __shared__ float sa[64][33];   // x tile  [row][k], padded
    __shared__ float sb[32][64];   // W tile  [k][col]

    const int tid = threadIdx.x;
    const int tx  = tid & 15;      // col group (16) -> cols tx*4..+3
    const int ty  = tid >> 4;      // row group (16) -> rows ty*4..+3
    const int row0 = blockIdx.x * 64;

    float acc[4][4] = {};

    for (int k0 = 0; k0 < 512; k0 += 32) {
        #pragma unroll
        for (int i = 0; i < 8; i++) {
            int idx = tid + i * 256;
            int r = idx >> 5, c = idx & 31;
            int gr = row0 + r, gc = k0 + c;
            sa[r][c] = (gr < NN && gc < FIN) ? x[(long long)gr * FIN + gc] : 0.f;
        }
        #pragma unroll
        for (int i = 0; i < 8; i++) {
            int idx = tid + i * 256;
            int r = idx >> 6, c = idx & 63;
            int gk = k0 + r;
            sb[r][c] = (gk < FIN) ? W1[gk * HID + c] : 0.f;
        }
        __syncthreads();

        #pragma unroll
        for (int kk = 0; kk < 32; kk++) {
            float av[4], bv[4];
            #pragma unroll
            for (int i = 0; i < 4; i++) av[i] = sa[ty * 4 + i][kk];
            #pragma unroll
            for (int j = 0; j < 4; j++) bv[j] = sb[kk][tx * 4 + j];
            #pragma unroll
            for (int i = 0; i < 4; i++)
                #pragma unroll
                for (int j = 0; j < 4; j++)
                    acc[i][j] += av[i] * bv[j];
        }
        __syncthreads();
    }

    #pragma unroll
    for (int i = 0; i < 4; i++) {
        int r = row0 + ty * 4 + i;
        if (r < NN) {
            float s = g_dinv[r];
            #pragma unroll
            for (int j = 0; j < 4; j++) {
                float v = acc[i][j] * s;
                int c = tx * 4 + j;
                g_h1s[(long long)r * HID + c] = v;
                g_t1 [(long long)r * HID + c] = v;   // self-loop init
            }
        }
    }
}

// ---------------- Aggregation 1: t1[d] += h1s[s]  (64 floats/edge) ---------
__global__ __launch_bounds__(256) void k_agg1() {
    unsigned gid = blockIdx.x * 256u + threadIdx.x;
    if (gid >= (unsigned)NE * HID) return;
    unsigned e = gid >> 6;          // /64
    unsigned c = gid & 63u;
    int s = g_src[e];
    int d = g_dst[e];
    atomicAdd(&g_t1[(long long)d * HID + c], g_h1s[(long long)s * HID + c]);
}

// ---------------- ReLU + bias: h = relu(dinv[r]*t1 + b1) -> g_h1s ----------
__global__ void k_relu_bias(const float* __restrict__ b1) {
    unsigned i = blockIdx.x * 256u + threadIdx.x;
    if (i >= (unsigned)NN * HID) return;
    int r = i >> 6, c = i & 63;
    float v = g_dinv[r] * g_t1[i] + b1[c];
    g_h1s[i] = v > 0.f ? v : 0.f;
}

// ---------------- GEMM2: gs = (h @ W2) * dinv[row]; out init = gs ----------
__global__ __launch_bounds__(256) void k_gemm2(const float* __restrict__ W2,
                                               float* __restrict__ out) {
    __shared__ float sw[HID * NCLS];     // 64*40 = 2560
    __shared__ float sx[32][65];

    const int tid = threadIdx.x;
    const int row0 = blockIdx.x * 32;

    for (int i = tid; i < HID * NCLS; i += 256) sw[i] = W2[i];
    for (int i = tid; i < 32 * HID; i += 256) {
        int r = i >> 6, c = i & 63;
        int gr = row0 + r;
        sx[r][c] = (gr < NN) ? g_h1s[(long long)gr * HID + c] : 0.f;
    }
    __syncthreads();

    int r  = tid >> 3;     // 0..31
    int cg = tid & 7;      // cols cg*5 .. cg*5+4
    float acc[5] = {};
    #pragma unroll
    for (int k = 0; k < HID; k++) {
        float xv = sx[r][k];
        #pragma unroll
        for (int j = 0; j < 5; j++)
            acc[j] += xv * sw[k * NCLS + cg * 5 + j];
    }
    int gr = row0 + r;
    if (gr < NN) {
        float s = g_dinv[gr];
        #pragma unroll
        for (int j = 0; j < 5; j++) {
            float v = acc[j] * s;
            long long o = (long long)gr * NCLS + cg * 5 + j;
            g_gs[o] = v;
            out[o]  = v;    // self-loop init of accumulator
        }
    }
}

// ---------------- Aggregation 2: out[d] += gs[s]  (40 floats/edge) ---------
__global__ __launch_bounds__(256) void k_agg2(float* __restrict__ out) {
    unsigned gid = blockIdx.x * 256u + threadIdx.x;
    if (gid >= (unsigned)NE * NCLS) return;
    unsigned e = gid / 40u;
    unsigned c = gid - e * 40u;
    int s = g_src[e];
    int d = g_dst[e];
    atomicAdd(&out[(long long)d * NCLS + c], g_gs[(long long)s * NCLS + c]);
}

// ---------------- final: v = dinv[r]*acc + b2, log_softmax (warp/row) ------
__global__ void k_final(const float* __restrict__ b2, float* __restrict__ out) {
    int warp = (blockIdx.x * blockDim.x + threadIdx.x) >> 5;
    int lane = threadIdx.x & 31;
    if (warp >= NN) return;
    float s = g_dinv[warp];
    long long base = (long long)warp * NCLS;

    float a0 = s * out[base + lane] + b2[lane];          // lanes 0..31
    bool act1 = lane < (NCLS - 32);                      // lanes 0..7 -> 32..39
    float a1 = act1 ? (s * out[base + 32 + lane] + b2[32 + lane]) : -INFINITY;

    float m = fmaxf(a0, a1);
    #pragma unroll
    for (int o = 16; o; o >>= 1) m = fmaxf(m, __shfl_xor_sync(0xFFFFFFFFu, m, o));

    float e = expf(a0 - m) + (act1 ? expf(a1 - m) : 0.f);
    #pragma unroll
    for (int o = 16; o; o >>= 1) e += __shfl_xor_sync(0xFFFFFFFFu, e, o);

    float lse = m + logf(e);
    out[base + lane] = a0 - lse;
    if (act1) out[base + 32 + lane] = a1 - lse;
}

// ---------------- launch ----------------------------------------------------
extern "C" void kernel_launch(void* const* d_in, const int* in_sizes, int n_in,
                              void* d_out, int out_size) {
    const float* x    = (const float*)d_in[0];
    const float* W1   = (const float*)d_in[1];
    const float* b1   = (const float*)d_in[2];
    const float* W2   = (const float*)d_in[3];
    const float* b2   = (const float*)d_in[4];
    const int*   eraw = (const int*)d_in[5];
    float* out = (float*)d_out;

    (void)in_sizes; (void)n_in; (void)out_size;

    // edge index normalization (dtype-agnostic)
    k_detect <<<1, 32>>>(eraw);
    k_convert<<<(2 * NE + 255) / 256, 256>>>(eraw);

    // degree / dinv
    k_deg_init <<<(NN + 255) / 256, 256>>>();
    k_deg_count<<<(NE + 255) / 256, 256>>>();
    k_make_dinv<<<(NN + 255) / 256, 256>>>();

    // layer 1
    k_gemm1<<<(NN + 63) / 64, 256>>>(x, W1);
    {
        long long tot = (long long)NE * HID;
        k_agg1<<<(unsigned)((tot + 255) / 256), 256>>>();
    }
    k_relu_bias<<<(NN * HID + 255) / 256, 256>>>(b1);

    // layer 2
    k_gemm2<<<(NN + 31) / 32, 256>>>(W2, out);
    {
        long long tot = (long long)NE * NCLS;
        k_agg2<<<(unsigned)((tot + 255) / 256), 256>>>(out);
    }

    // bias + log_softmax (one warp per row)
    k_final<<<(NN + 7) / 8, 256>>>(b2, out);
}

// round 3
// speedup vs baseline: 1.6555x; 1.6555x over previous
#include <cuda_runtime.h>
#include <math.h>

// Problem constants
static constexpr int NN   = 100000;   // nodes
static constexpr int NE   = 1600000;  // edges
static constexpr int FIN  = 500;
static constexpr int HID  = 64;
static constexpr int NCLS = 40;

// ---------------- scratch (device globals; no cudaMalloc allowed) ----------
__device__ float g_dinv[NN];              // deg -> dinv (in place)
__device__ float g_h1s [NN * HID];        // h1 * dinv[row]; later relu(h)
__device__ float g_t1  [NN * HID];        // layer-1 aggregation accumulator
__device__ float g_gs  [NN * NCLS];       // g2 * dinv[row]
__device__ int   g_src [NE];
__device__ int   g_dst [NE];
__device__ int   g_is64;

// ---------------- vectorized global reduction ------------------------------
__device__ __forceinline__ void red_add_v4(float* p, float4 v) {
    asm volatile("red.global.add.v4.f32 [%0], {%1, %2, %3, %4};"
                 :: "l"(p), "f"(v.x), "f"(v.y), "f"(v.z), "f"(v.w)
                 : "memory");
}

// ---------------- edge-index dtype detection + conversion ------------------
__global__ void k_detect(const int* __restrict__ e) {
    if (threadIdx.x == 0 && blockIdx.x == 0) {
        int all0 = 1;
        #pragma unroll 1
        for (int i = 0; i < 64; i++) all0 &= (e[2 * i + 1] == 0);
        g_is64 = all0;
    }
}

__global__ void k_convert(const int* __restrict__ e) {
    int i = blockIdx.x * blockDim.x + threadIdx.x;
    if (i >= 2 * NE) return;
    int v = g_is64 ? e[2 * i] : e[i];   // low word of int64, or int32 directly
    if (i < NE) g_src[i] = v;
    else        g_dst[i - NE] = v;
}

// ---------------- degree / dinv --------------------------------------------
__global__ void k_deg_init() {
    int i = blockIdx.x * blockDim.x + threadIdx.x;
    if (i < NN) g_dinv[i] = 1.0f;   // self-loop contributes 1
}

__global__ void k_deg_count() {
    int e = blockIdx.x * blockDim.x + threadIdx.x;
    if (e < NE) atomicAdd(&g_dinv[g_dst[e]], 1.0f);
}

__global__ void k_make_dinv() {
    int i = blockIdx.x * blockDim.x + threadIdx.x;
    if (i < NN) g_dinv[i] = rsqrtf(g_dinv[i]);
}

// ---------------- GEMM1: h1s = (x @ W1) * dinv[row] ------------------------
// BM=64, BN=64(=HID), BK=32, 256 threads, 4x4 micro-tile per thread.
__global__ __launch_bounds__(256) void k_gemm1(const float* __restrict__ x,
                                               const float* __restrict__ W1) {
    __shared__ float sa[64][33];   // x tile  [row][k], padded
    __shared__ float sb[32][64];   // W tile  [k][col]

    const int tid = threadIdx.x;
    const int tx  = tid & 15;
    const int ty  = tid >> 4;
    const int row0 = blockIdx.x * 64;

    float acc[4][4] = {};

    for (int k0 = 0; k0 < 512; k0 += 32) {
        #pragma unroll
        for (int i = 0; i < 8; i++) {
            int idx = tid + i * 256;
            int r = idx >> 5, c = idx & 31;
            int gr = row0 + r, gc = k0 + c;
            sa[r][c] = (gr < NN && gc < FIN) ? x[(long long)gr * FIN + gc] : 0.f;
        }
        #pragma unroll
        for (int i = 0; i < 8; i++) {
            int idx = tid + i * 256;
            int r = idx >> 6, c = idx & 63;
            int gk = k0 + r;
            sb[r][c] = (gk < FIN) ? W1[gk * HID + c] : 0.f;
        }
        __syncthreads();

        #pragma unroll
        for (int kk = 0; kk < 32; kk++) {
            float av[4], bv[4];
            #pragma unroll
            for (int i = 0; i < 4; i++) av[i] = sa[ty * 4 + i][kk];
            #pragma unroll
            for (int j = 0; j < 4; j++) bv[j] = sb[kk][tx * 4 + j];
            #pragma unroll
            for (int i = 0; i < 4; i++)
                #pragma unroll
                for (int j = 0; j < 4; j++)
                    acc[i][j] += av[i] * bv[j];
        }
        __syncthreads();
    }

    #pragma unroll
    for (int i = 0; i < 4; i++) {
        int r = row0 + ty * 4 + i;
        if (r < NN) {
            float s = g_dinv[r];
            #pragma unroll
            for (int j = 0; j < 4; j++) {
                float v = acc[i][j] * s;
                int c = tx * 4 + j;
                g_h1s[r * HID + c] = v;
                g_t1 [r * HID + c] = v;   // self-loop init
            }
        }
    }
}

// ---------------- Aggregation 1: t1[d] += h1s[s]  (16 float4/edge) ---------
__global__ __launch_bounds__(256) void k_agg1() {
    unsigned gid = blockIdx.x * 256u + threadIdx.x;
    if (gid >= (unsigned)NE * 16u) return;
    unsigned e  = gid >> 4;            // edge
    unsigned c4 = (gid & 15u) << 2;    // float offset 0,4,...,60
    int s = g_src[e];
    int d = g_dst[e];
    float4 v = *(const float4*)&g_h1s[s * HID + c4];
    red_add_v4(&g_t1[d * HID + c4], v);
}

// ---------------- ReLU + bias: h = relu(dinv[r]*t1 + b1) -> g_h1s ----------
__global__ void k_relu_bias(const float* __restrict__ b1) {
    unsigned i = blockIdx.x * 256u + threadIdx.x;
    if (i >= (unsigned)NN * HID) return;
    int r = i >> 6, c = i & 63;
    float v = g_dinv[r] * g_t1[i] + b1[c];
    g_h1s[i] = v > 0.f ? v : 0.f;
}

// ---------------- GEMM2: gs = (h @ W2) * dinv[row]; out init = gs ----------
__global__ __launch_bounds__(256) void k_gemm2(const float* __restrict__ W2,
                                               float* __restrict__ out) {
    __shared__ float sw[HID * NCLS];     // 64*40 = 2560
    __shared__ float sx[32][65];

    const int tid = threadIdx.x;
    const int row0 = blockIdx.x * 32;

    for (int i = tid; i < HID * NCLS; i += 256) sw[i] = W2[i];
    for (int i = tid; i < 32 * HID; i += 256) {
        int r = i >> 6, c = i & 63;
        int gr = row0 + r;
        sx[r][c] = (gr < NN) ? g_h1s[gr * HID + c] : 0.f;
    }
    __syncthreads();

    int r  = tid >> 3;     // 0..31
    int cg = tid & 7;      // cols cg*5 .. cg*5+4
    float acc[5] = {};
    #pragma unroll
    for (int k = 0; k < HID; k++) {
        float xv = sx[r][k];
        #pragma unroll
        for (int j = 0; j < 5; j++)
            acc[j] += xv * sw[k * NCLS + cg * 5 + j];
    }
    int gr = row0 + r;
    if (gr < NN) {
        float s = g_dinv[gr];
        #pragma unroll
        for (int j = 0; j < 5; j++) {
            float v = acc[j] * s;
            int o = gr * NCLS + cg * 5 + j;
            g_gs[o] = v;
            out[o]  = v;    // self-loop init of accumulator
        }
    }
}

// ---------------- Aggregation 2: out[d] += gs[s]  (10 float4/edge) ---------
__global__ __launch_bounds__(256) void k_agg2(float* __restrict__ out) {
    unsigned gid = blockIdx.x * 256u + threadIdx.x;
    if (gid >= (unsigned)NE * 10u) return;
    unsigned e  = gid / 10u;
    unsigned c4 = (gid - e * 10u) << 2;   // 0,4,...,36
    int s = g_src[e];
    int d = g_dst[e];
    float4 v = *(const float4*)&g_gs[s * NCLS + c4];
    red_add_v4(&out[d * NCLS + c4], v);
}

// ---------------- final: v = dinv[r]*acc + b2, log_softmax (warp/row) ------
__global__ void k_final(const float* __restrict__ b2, float* __restrict__ out) {
    int warp = (blockIdx.x * blockDim.x + threadIdx.x) >> 5;
    int lane = threadIdx.x & 31;
    if (warp >= NN) return;
    float s = g_dinv[warp];
    int base = warp * NCLS;

    float a0 = s * out[base + lane] + b2[lane];          // lanes 0..31
    bool act1 = lane < (NCLS - 32);                      // lanes 0..7 -> 32..39
    float a1 = act1 ? (s * out[base + 32 + lane] + b2[32 + lane]) : -INFINITY;

    float m = fmaxf(a0, a1);
    #pragma unroll
    for (int o = 16; o; o >>= 1) m = fmaxf(m, __shfl_xor_sync(0xFFFFFFFFu, m, o));

    float e = expf(a0 - m) + (act1 ? expf(a1 - m) : 0.f);
    #pragma unroll
    for (int o = 16; o; o >>= 1) e += __shfl_xor_sync(0xFFFFFFFFu, e, o);

    float lse = m + logf(e);
    out[base + lane] = a0 - lse;
    if (act1) out[base + 32 + lane] = a1 - lse;
}

// ---------------- launch ----------------------------------------------------
extern "C" void kernel_launch(void* const* d_in, const int* in_sizes, int n_in,
                              void* d_out, int out_size) {
    const float* x    = (const float*)d_in[0];
    const float* W1   = (const float*)d_in[1];
    const float* b1   = (const float*)d_in[2];
    const float* W2   = (const float*)d_in[3];
    const float* b2   = (const float*)d_in[4];
    const int*   eraw = (const int*)d_in[5];
    float* out = (float*)d_out;

    (void)in_sizes; (void)n_in; (void)out_size;

    // edge index normalization (dtype-agnostic)
    k_detect <<<1, 32>>>(eraw);
    k_convert<<<(2 * NE + 255) / 256, 256>>>(eraw);

    // degree / dinv
    k_deg_init <<<(NN + 255) / 256, 256>>>();
    k_deg_count<<<(NE + 255) / 256, 256>>>();
    k_make_dinv<<<(NN + 255) / 256, 256>>>();

    // layer 1
    k_gemm1<<<(NN + 63) / 64, 256>>>(x, W1);
    {
        unsigned tot = (unsigned)NE * 16u;
        k_agg1<<<(tot + 255) / 256, 256>>>();
    }
    k_relu_bias<<<(NN * HID + 255) / 256, 256>>>(b1);

    // layer 2
    k_gemm2<<<(NN + 31) / 32, 256>>>(W2, out);
    {
        unsigned tot = (unsigned)NE * 10u;
        k_agg2<<<(tot + 255) / 256, 256>>>(out);
    }

    // bias + log_softmax (one warp per row)
    k_final<<<(NN + 7) / 8, 256>>>(b2, out);
}